// round 1
// baseline (speedup 1.0000x reference)
#include <cuda_runtime.h>
#include <math.h>

// Problem constants (fixed by the dataset instance)
#define NG   8192     // groups
#define SS   64       // samples per group
#define DD   128      // feature dim
#define HH   256      // hidden dim
#define KK   8        // clusters
#define GPB  8        // groups per block (1 warp each)
#define EPSV 0.01f

// Output layout: [rep G*D][mixture G*K][scale G][alpha G][beta G]
#define OFF_MIX   (NG * DD)
#define OFF_SCALE (OFF_MIX + NG * KK)
#define OFF_ALPHA (OFF_SCALE + NG)
#define OFF_BETA  (OFF_ALPHA + NG)

__device__ __forceinline__ float softplus_f(float v) {
    return v > 20.0f ? v : log1pf(expf(v));
}

__global__ __launch_bounds__(256, 4)
void cluster_model_kernel(
    const float* __restrict__ x,        // [N, D]
    const float* __restrict__ y,        // [N, 1]
    const float* __restrict__ anchor_x, // [G, D]
    const float* __restrict__ anchor_y, // [G, 1]
    const float* __restrict__ W1,       // [D, H]
    const float* __restrict__ b1,       // [H]
    const float* __restrict__ W2,       // [H, K+2]
    const float* __restrict__ b2,       // [K+2]
    float* __restrict__ out)
{
    __shared__ float rep_s[GPB][DD];
    __shared__ float h_s[GPB][HH + 1];   // +1 pad: bank-spread across groups
    __shared__ float o_s[GPB][12];

    const int tid = threadIdx.x;
    const int w   = tid >> 5;            // warp = local group
    const int l   = tid & 31;            // lane = 4 dims
    const int g   = blockIdx.x * GPB + w;

    // ---------------- Phase 1: per-group statistics (1 warp / group) ----------
    {
        const float4* xg = reinterpret_cast<const float4*>(x + (size_t)g * SS * DD);
        const float*  yg = y + (size_t)g * SS;
        float4 a4 = reinterpret_cast<const float4*>(anchor_x + (size_t)g * DD)[l];
        float  ayv = anchor_y[g];

        float4 sx  = make_float4(0.f, 0.f, 0.f, 0.f);
        float4 sxy = make_float4(0.f, 0.f, 0.f, 0.f);
        float  sxx = 0.f, sy = 0.f;

        #pragma unroll 8
        for (int i = 0; i < SS; ++i) {
            float4 xv = xg[i * (DD / 4) + l];
            float  yr = yg[i] - ayv;
            float xr0 = xv.x - a4.x;
            float xr1 = xv.y - a4.y;
            float xr2 = xv.z - a4.z;
            float xr3 = xv.w - a4.w;
            sx.x += xr0; sx.y += xr1; sx.z += xr2; sx.w += xr3;
            sxy.x = fmaf(xr0, yr, sxy.x);
            sxy.y = fmaf(xr1, yr, sxy.y);
            sxy.z = fmaf(xr2, yr, sxy.z);
            sxy.w = fmaf(xr3, yr, sxy.w);
            sxx = fmaf(xr0, xr0, sxx);
            sxx = fmaf(xr1, xr1, sxx);
            sxx = fmaf(xr2, xr2, sxx);
            sxx = fmaf(xr3, xr3, sxx);
            sy  += yr;   // identical in every lane (uniform)
        }

        // warp-reduce scalar stats
        float tot = sx.x + sx.y + sx.z + sx.w;
        #pragma unroll
        for (int o = 16; o > 0; o >>= 1) {
            sxx += __shfl_xor_sync(0xFFFFFFFFu, sxx, o);
            tot += __shfl_xor_sync(0xFFFFFFFFu, tot, o);
        }

        const float nD      = (float)(SS * DD);                   // 8192
        const float var     = (sxx - tot * tot / nD) / (nD - 1.0f);
        const float inv_var = 1.0f / var;
        const float c       = sy / (float)SS;                     // sy/n
        const float inv_nm1 = 1.0f / (float)(SS - 1);             // 1/63

        float4 rep;
        rep.x = (sxy.x - sx.x * c) * inv_nm1 * inv_var;
        rep.y = (sxy.y - sx.y * c) * inv_nm1 * inv_var;
        rep.z = (sxy.z - sx.z * c) * inv_nm1 * inv_var;
        rep.w = (sxy.w - sx.w * c) * inv_nm1 * inv_var;

        reinterpret_cast<float4*>(out + (size_t)g * DD)[l] = rep;  // rep output
        *reinterpret_cast<float4*>(&rep_s[w][4 * l]) = rep;
    }
    __syncthreads();

    // ---------------- Phase 2a: h = tanh(rep @ W1 + b1), thread = hidden j ----
    {
        const int j = tid;  // 0..255
        float acc[GPB];
        float bj = b1[j];
        #pragma unroll
        for (int gg = 0; gg < GPB; ++gg) acc[gg] = bj;

        #pragma unroll 4
        for (int d = 0; d < DD; d += 4) {
            float w0 = W1[(d + 0) * HH + j];
            float w1v = W1[(d + 1) * HH + j];
            float w2v = W1[(d + 2) * HH + j];
            float w3v = W1[(d + 3) * HH + j];
            #pragma unroll
            for (int gg = 0; gg < GPB; ++gg) {
                float4 r = *reinterpret_cast<const float4*>(&rep_s[gg][d]);
                acc[gg] = fmaf(r.x, w0, acc[gg]);
                acc[gg] = fmaf(r.y, w1v, acc[gg]);
                acc[gg] = fmaf(r.z, w2v, acc[gg]);
                acc[gg] = fmaf(r.w, w3v, acc[gg]);
            }
        }
        #pragma unroll
        for (int gg = 0; gg < GPB; ++gg) h_s[gg][j] = tanhf(acc[gg]);
    }
    __syncthreads();

    // ---------------- Phase 2b: out = h @ W2 + b2 (80 items: 8 groups x 10) ---
    if (tid < GPB * (KK + 2)) {
        const int gg = tid & (GPB - 1);
        const int k  = tid >> 3;            // 0..9
        float acc = b2[k];
        #pragma unroll 8
        for (int j = 0; j < HH; ++j) {
            acc = fmaf(h_s[gg][j], W2[j * (KK + 2) + k], acc);
        }
        o_s[gg][k] = acc;
    }
    __syncthreads();

    // ---------------- Phase 2c: heads (1 thread / group) ----------------------
    if (tid < GPB) {
        const int gg = tid;
        const int gl = blockIdx.x * GPB + gg;

        float alpha = softplus_f(o_s[gg][0]) * (1.0f - EPSV) + EPSV;
        float beta  = softplus_f(o_s[gg][1]) * (1.0f - EPSV) + EPSV;

        float m = -INFINITY;
        #pragma unroll
        for (int k = 0; k < KK; ++k) m = fmaxf(m, o_s[gg][2 + k]);
        float e[KK];
        float s = 0.f;
        #pragma unroll
        for (int k = 0; k < KK; ++k) { e[k] = expf(o_s[gg][2 + k] - m); s += e[k]; }
        float inv = 1.0f / s;
        #pragma unroll
        for (int k = 0; k < KK; ++k) out[OFF_MIX + (size_t)gl * KK + k] = e[k] * inv;

        out[OFF_SCALE + gl] = sqrtf(beta / alpha);
        out[OFF_ALPHA + gl] = alpha;
        out[OFF_BETA  + gl] = beta;
    }
}

extern "C" void kernel_launch(void* const* d_in, const int* in_sizes, int n_in,
                              void* d_out, int out_size) {
    // inputs (metadata order): index, x, y, anchor_x, anchor_y, W1, b1, W2, b2
    const float* x        = (const float*)d_in[1];
    const float* y        = (const float*)d_in[2];
    const float* anchor_x = (const float*)d_in[3];
    const float* anchor_y = (const float*)d_in[4];
    const float* W1       = (const float*)d_in[5];
    const float* b1       = (const float*)d_in[6];
    const float* W2       = (const float*)d_in[7];
    const float* b2       = (const float*)d_in[8];
    float* out            = (float*)d_out;

    dim3 grid(NG / GPB);   // 1024 blocks
    dim3 block(256);
    cluster_model_kernel<<<grid, block>>>(x, y, anchor_x, anchor_y,
                                          W1, b1, W2, b2, out);
}